// round 1
// baseline (speedup 1.0000x reference)
#include <cuda_runtime.h>

#define H_IMG 1080
#define W_IMG 1920
#define GY 16
#define GX 16
#define GW 8
#define NPIX (H_IMG * W_IMG)

__global__ __launch_bounds__(256) void bilateral_grid_kernel(
    const float* __restrict__ rgb,     // (3, H, W)
    const float* __restrict__ grids,   // (NUM, GY, GX, GW, 12)
    const int*   __restrict__ idxp,    // scalar
    float*       __restrict__ out)     // [affine (NPIX*12) | res (NPIX*3)]
{
    int n = blockIdx.x * blockDim.x + threadIdx.x;
    if (n >= NPIX) return;

    int y = n / W_IMG;
    int x = n - y * W_IMG;

    float r = rgb[n];
    float g = rgb[NPIX + n];
    float b = rgb[2 * NPIX + n];

    float gray = 0.299f * r + 0.587f * g + 0.114f * b;

    const float* grid = grids + (size_t)idxp[0] * (GY * GX * GW * 12);

    // align_corners linspace coords
    float gy = (float)y * ((float)(GY - 1) / (float)(H_IMG - 1));
    float gx = (float)x * ((float)(GX - 1) / (float)(W_IMG - 1));
    float gz = fminf(fmaxf(gray, 0.0f), 1.0f) * (float)(GW - 1);

    float fy = floorf(gy); float wy = gy - fy;
    float fx = floorf(gx); float wx = gx - fx;
    float fz = floorf(gz); float wz = gz - fz;

    int y0 = min(max((int)fy, 0), GY - 1); int y1 = min(y0 + 1, GY - 1);
    int x0 = min(max((int)fx, 0), GX - 1); int x1 = min(x0 + 1, GX - 1);
    int z0 = min(max((int)fz, 0), GW - 1); int z1 = min(z0 + 1, GW - 1);

    float wyv[2] = {1.0f - wy, wy};
    float wxv[2] = {1.0f - wx, wx};
    float wzv[2] = {1.0f - wz, wz};
    int   yv[2]  = {y0, y1};
    int   xv[2]  = {x0, x1};
    int   zv[2]  = {z0, z1};

    float4 a0 = make_float4(0.f, 0.f, 0.f, 0.f);
    float4 a1 = make_float4(0.f, 0.f, 0.f, 0.f);
    float4 a2 = make_float4(0.f, 0.f, 0.f, 0.f);

    #pragma unroll
    for (int iy = 0; iy < 2; iy++) {
        #pragma unroll
        for (int ix = 0; ix < 2; ix++) {
            #pragma unroll
            for (int iz = 0; iz < 2; iz++) {
                float w = wyv[iy] * wxv[ix] * wzv[iz];
                const float4* p = reinterpret_cast<const float4*>(
                    grid + ((size_t)(yv[iy] * GX + xv[ix]) * GW + zv[iz]) * 12);
                float4 c0 = __ldg(p + 0);
                float4 c1 = __ldg(p + 1);
                float4 c2 = __ldg(p + 2);
                a0.x += w * c0.x; a0.y += w * c0.y; a0.z += w * c0.z; a0.w += w * c0.w;
                a1.x += w * c1.x; a1.y += w * c1.y; a1.z += w * c1.z; a1.w += w * c1.w;
                a2.x += w * c2.x; a2.y += w * c2.y; a2.z += w * c2.z; a2.w += w * c2.w;
            }
        }
    }

    // affine_mat: out[n*12 + i*4 + j]
    float4* aout = reinterpret_cast<float4*>(out) + (size_t)n * 3;
    aout[0] = a0;
    aout[1] = a1;
    aout[2] = a2;

    // res_rgb at offset 12*NPIX
    float* res = out + (size_t)12 * NPIX + (size_t)n * 3;
    res[0] = a0.x * r + a0.y * g + a0.z * b + a0.w;
    res[1] = a1.x * r + a1.y * g + a1.z * b + a1.w;
    res[2] = a2.x * r + a2.y * g + a2.z * b + a2.w;
}

extern "C" void kernel_launch(void* const* d_in, const int* in_sizes, int n_in,
                              void* d_out, int out_size) {
    const float* rgb   = (const float*)d_in[0];
    const float* grids = (const float*)d_in[1];
    const int*   idx   = (const int*)d_in[2];
    float* out = (float*)d_out;

    const int threads = 256;
    const int blocks  = (NPIX + threads - 1) / threads;
    bilateral_grid_kernel<<<blocks, threads>>>(rgb, grids, idx, out);
}

// round 2
// speedup vs baseline: 1.1597x; 1.1597x over previous
#include <cuda_runtime.h>

#define H_IMG 1080
#define W_IMG 1920
#define GY 16
#define GX 16
#define GW 8
#define NPIX (H_IMG * W_IMG)

#define BX 192                       // pixels per block, one row strip
#define BLK_PER_ROW (W_IMG / BX)     // 10

#define SX (15.0f / 1919.0f)         // (GX-1)/(W_IMG-1)
#define SY (15.0f / 1079.0f)         // (GY-1)/(H_IMG-1)

__global__ __launch_bounds__(BX) void bilateral_grid_kernel(
    const float* __restrict__ rgb,     // (3, H, W)
    const float* __restrict__ grids,   // (NUM, GY, GX, GW, 12)
    const int*   __restrict__ idxp,    // scalar
    float*       __restrict__ out)     // [affine (NPIX*12) | res (NPIX*3)]
{
    __shared__ __align__(16) float g2[4 * GW * 12];   // y-interpolated grid, 4 x-cells
    __shared__ __align__(16) float rstage[BX * 3];    // res_rgb staging

    const int tid   = threadIdx.x;
    const int row   = blockIdx.y;
    const int strip = blockIdx.x;
    const int xpix0 = strip * BX;

    // ---- block-uniform y interpolation setup ----
    float gyv = (float)row * SY;
    float fy  = floorf(gyv);
    float wy  = gyv - fy;
    int y0 = min(max((int)fy, 0), GY - 1);
    int y1 = min(y0 + 1, GY - 1);
    float wy0 = 1.0f - wy, wy1 = wy;

    // x-cell base for this strip
    int xbase = (int)floorf((float)xpix0 * SX);

    const float* grid = grids + (size_t)idxp[0] * (GY * GX * GW * 12);

    // ---- cooperative build of G2[xq][z][c] = lerp over y ----
    #pragma unroll
    for (int t = tid; t < 4 * GW * 12; t += BX) {
        int xq  = t / (GW * 12);
        int rem = t - xq * (GW * 12);
        int zq  = rem / 12;
        int c   = rem - zq * 12;
        int xc  = min(xbase + xq, GX - 1);
        float a = __ldg(grid + ((size_t)(y0 * GX + xc) * GW + zq) * 12 + c);
        float b = __ldg(grid + ((size_t)(y1 * GX + xc) * GW + zq) * 12 + c);
        g2[t] = wy0 * a + wy1 * b;
    }
    __syncthreads();

    // ---- per-pixel work ----
    const int x = xpix0 + tid;
    const int n = row * W_IMG + x;

    float r = rgb[n];
    float g = rgb[NPIX + n];
    float b = rgb[2 * NPIX + n];

    float gray = 0.299f * r + 0.587f * g + 0.114f * b;

    // x interpolation (per-lane)
    float gxv = (float)x * SX;
    float fx  = floorf(gxv);
    float wx  = gxv - fx;
    int x0 = min(max((int)fx, 0), GX - 1);
    int x1 = min(x0 + 1, GX - 1);
    int x0l = x0 - xbase;
    int x1l = x1 - xbase;

    // z interpolation (per-lane, gray-dependent)
    float gz = __saturatef(gray) * (float)(GW - 1);
    float fz = floorf(gz);
    float wz = gz - fz;
    int z0 = min(max((int)fz, 0), GW - 1);
    int z1 = min(z0 + 1, GW - 1);

    float w00 = (1.0f - wx) * (1.0f - wz);   // (x0, z0)
    float w01 = (1.0f - wx) * wz;            // (x0, z1)
    float w10 = wx * (1.0f - wz);            // (x1, z0)
    float w11 = wx * wz;                     // (x1, z1)

    const float4* c00 = reinterpret_cast<const float4*>(g2 + (x0l * GW + z0) * 12);
    const float4* c01 = reinterpret_cast<const float4*>(g2 + (x0l * GW + z1) * 12);
    const float4* c10 = reinterpret_cast<const float4*>(g2 + (x1l * GW + z0) * 12);
    const float4* c11 = reinterpret_cast<const float4*>(g2 + (x1l * GW + z1) * 12);

    float4 a0, a1, a2;
    {
        float4 p00, p01, p10, p11;
        p00 = c00[0]; p01 = c01[0]; p10 = c10[0]; p11 = c11[0];
        a0.x = w00*p00.x + w01*p01.x + w10*p10.x + w11*p11.x;
        a0.y = w00*p00.y + w01*p01.y + w10*p10.y + w11*p11.y;
        a0.z = w00*p00.z + w01*p01.z + w10*p10.z + w11*p11.z;
        a0.w = w00*p00.w + w01*p01.w + w10*p10.w + w11*p11.w;
        p00 = c00[1]; p01 = c01[1]; p10 = c10[1]; p11 = c11[1];
        a1.x = w00*p00.x + w01*p01.x + w10*p10.x + w11*p11.x;
        a1.y = w00*p00.y + w01*p01.y + w10*p10.y + w11*p11.y;
        a1.z = w00*p00.z + w01*p01.z + w10*p10.z + w11*p11.z;
        a1.w = w00*p00.w + w01*p01.w + w10*p10.w + w11*p11.w;
        p00 = c00[2]; p01 = c01[2]; p10 = c10[2]; p11 = c11[2];
        a2.x = w00*p00.x + w01*p01.x + w10*p10.x + w11*p11.x;
        a2.y = w00*p00.y + w01*p01.y + w10*p10.y + w11*p11.y;
        a2.z = w00*p00.z + w01*p01.z + w10*p10.z + w11*p11.z;
        a2.w = w00*p00.w + w01*p01.w + w10*p10.w + w11*p11.w;
    }

    // affine_mat: out[n*12 ...], 3x STG.128 coalesced
    float4* aout = reinterpret_cast<float4*>(out) + (size_t)n * 3;
    aout[0] = a0;
    aout[1] = a1;
    aout[2] = a2;

    // res_rgb -> smem staging (stride-3 floats: conflict-free, gcd(3,32)=1)
    rstage[tid * 3 + 0] = a0.x * r + a0.y * g + a0.z * b + a0.w;
    rstage[tid * 3 + 1] = a1.x * r + a1.y * g + a1.z * b + a1.w;
    rstage[tid * 3 + 2] = a2.x * r + a2.y * g + a2.z * b + a2.w;
    __syncthreads();

    // coalesced float4 writeback of res block
    const int nbase = row * W_IMG + xpix0;
    float4* rout = reinterpret_cast<float4*>(out + (size_t)12 * NPIX + (size_t)nbase * 3);
    if (tid < (BX * 3) / 4) {
        rout[tid] = reinterpret_cast<float4*>(rstage)[tid];
    }
}

extern "C" void kernel_launch(void* const* d_in, const int* in_sizes, int n_in,
                              void* d_out, int out_size) {
    const float* rgb   = (const float*)d_in[0];
    const float* grids = (const float*)d_in[1];
    const int*   idx   = (const int*)d_in[2];
    float* out = (float*)d_out;

    dim3 grid(BLK_PER_ROW, H_IMG);
    bilateral_grid_kernel<<<grid, BX>>>(rgb, grids, idx, out);
}

// round 3
// speedup vs baseline: 1.2333x; 1.0635x over previous
#include <cuda_runtime.h>

#define H_IMG 1080
#define W_IMG 1920
#define GY 16
#define GX 16
#define GW 8
#define NPIX (H_IMG * W_IMG)

#define BX 192                  // threads per block
#define PXT 2                   // pixels per thread
#define STRIP (BX * PXT)        // 384 pixels per strip
#define BLK_PER_ROW (W_IMG / STRIP)  // 5
#define NC 5                    // x-cells covered by one strip (384*SX ~= 3.0 + x1)

#define SX (15.0f / 1919.0f)
#define SY (15.0f / 1079.0f)

__global__ __launch_bounds__(BX) void bilateral_grid_kernel(
    const float* __restrict__ rgb,
    const float* __restrict__ grids,
    const int*   __restrict__ idxp,
    float*       __restrict__ out)
{
    __shared__ __align__(16) float g2[NC * GW * 12];   // 480 floats = 120 float4

    const int tid   = threadIdx.x;
    const int row   = blockIdx.y;
    const int xpix0 = blockIdx.x * STRIP;

    // block-uniform y lerp
    float gyv = (float)row * SY;
    float fy  = floorf(gyv);
    float wy  = gyv - fy;
    int y0 = min((int)fy, GY - 1);
    int y1 = min(y0 + 1, GY - 1);
    float wy0 = 1.0f - wy, wy1 = wy;

    const float* grid = grids + (size_t)idxp[0] * (GY * GX * GW * 12);
    int xbase = (int)((float)xpix0 * SX);

    // ---- vectorized g2 build: 120 float4 work items, one shot ----
    if (tid < NC * GW * 3) {
        int xq  = tid / (GW * 3);
        int rem = tid - xq * (GW * 3);
        int zq  = rem / 3;
        int c4  = rem - zq * 3;
        int xc  = min(xbase + xq, GX - 1);
        const float4* pa = reinterpret_cast<const float4*>(
            grid + ((size_t)(y0 * GX + xc) * GW + zq) * 12) + c4;
        const float4* pb = reinterpret_cast<const float4*>(
            grid + ((size_t)(y1 * GX + xc) * GW + zq) * 12) + c4;
        float4 a = __ldg(pa);
        float4 b = __ldg(pb);
        float4 o;
        o.x = wy0 * a.x + wy1 * b.x;
        o.y = wy0 * a.y + wy1 * b.y;
        o.z = wy0 * a.z + wy1 * b.z;
        o.w = wy0 * a.w + wy1 * b.w;
        reinterpret_cast<float4*>(g2)[tid] = o;
    }
    __syncthreads();

    // ---- per-pixel work: PXT strided pixels ----
    #pragma unroll
    for (int k = 0; k < PXT; k++) {
        const int x = xpix0 + tid + k * BX;
        const int n = row * W_IMG + x;

        float r = rgb[n];
        float g = rgb[NPIX + n];
        float b = rgb[2 * NPIX + n];

        float gray = 0.299f * r + 0.587f * g + 0.114f * b;

        float gxv = (float)x * SX;
        float fx  = floorf(gxv);
        float wx  = gxv - fx;
        int x0 = min((int)fx, GX - 1);
        int x1 = min(x0 + 1, GX - 1);
        int x0l = x0 - xbase;
        int x1l = x1 - xbase;

        float gz = __saturatef(gray) * (float)(GW - 1);
        float fz = floorf(gz);
        float wz = gz - fz;
        int z0 = min(max((int)fz, 0), GW - 1);
        int z1 = min(z0 + 1, GW - 1);

        float w00 = (1.0f - wx) * (1.0f - wz);
        float w01 = (1.0f - wx) * wz;
        float w10 = wx * (1.0f - wz);
        float w11 = wx * wz;

        const float4* c00 = reinterpret_cast<const float4*>(g2 + (x0l * GW + z0) * 12);
        const float4* c01 = reinterpret_cast<const float4*>(g2 + (x0l * GW + z1) * 12);
        const float4* c10 = reinterpret_cast<const float4*>(g2 + (x1l * GW + z0) * 12);
        const float4* c11 = reinterpret_cast<const float4*>(g2 + (x1l * GW + z1) * 12);

        float4 a0, a1, a2;
        {
            float4 p00, p01, p10, p11;
            p00 = c00[0]; p01 = c01[0]; p10 = c10[0]; p11 = c11[0];
            a0.x = w00*p00.x + w01*p01.x + w10*p10.x + w11*p11.x;
            a0.y = w00*p00.y + w01*p01.y + w10*p10.y + w11*p11.y;
            a0.z = w00*p00.z + w01*p01.z + w10*p10.z + w11*p11.z;
            a0.w = w00*p00.w + w01*p01.w + w10*p10.w + w11*p11.w;
            p00 = c00[1]; p01 = c01[1]; p10 = c10[1]; p11 = c11[1];
            a1.x = w00*p00.x + w01*p01.x + w10*p10.x + w11*p11.x;
            a1.y = w00*p00.y + w01*p01.y + w10*p10.y + w11*p11.y;
            a1.z = w00*p00.z + w01*p01.z + w10*p10.z + w11*p11.z;
            a1.w = w00*p00.w + w01*p01.w + w10*p10.w + w11*p11.w;
            p00 = c00[2]; p01 = c01[2]; p10 = c10[2]; p11 = c11[2];
            a2.x = w00*p00.x + w01*p01.x + w10*p10.x + w11*p11.x;
            a2.y = w00*p00.y + w01*p01.y + w10*p10.y + w11*p11.y;
            a2.z = w00*p00.z + w01*p01.z + w10*p10.z + w11*p11.z;
            a2.w = w00*p00.w + w01*p01.w + w10*p10.w + w11*p11.w;
        }

        float4* aout = reinterpret_cast<float4*>(out) + (size_t)n * 3;
        aout[0] = a0;
        aout[1] = a1;
        aout[2] = a2;

        float* res = out + (size_t)12 * NPIX + (size_t)n * 3;
        res[0] = a0.x * r + a0.y * g + a0.z * b + a0.w;
        res[1] = a1.x * r + a1.y * g + a1.z * b + a1.w;
        res[2] = a2.x * r + a2.y * g + a2.z * b + a2.w;
    }
}

extern "C" void kernel_launch(void* const* d_in, const int* in_sizes, int n_in,
                              void* d_out, int out_size) {
    const float* rgb   = (const float*)d_in[0];
    const float* grids = (const float*)d_in[1];
    const int*   idx   = (const int*)d_in[2];
    float* out = (float*)d_out;

    dim3 grid(BLK_PER_ROW, H_IMG);
    bilateral_grid_kernel<<<grid, BX>>>(rgb, grids, idx, out);
}